// round 17
// baseline (speedup 1.0000x reference)
#include <cuda_runtime.h>
#include <cuda_fp16.h>
#include <cstdint>

// Problem constants (ParacrineCascade: B=32, N=2048, D=128, K=3)
#define B_     32
#define N_     2048
#define D_     128
#define QT     128                // queries per CTA (1 CTA/SM)
#define CT     128                // candidates per tile
#define NTILE  (N_ / CT)          // 16
#define NT     512                // threads (16 warps: 4m x 4n, warp tile 32x32)

// smem byte offsets
#define OFF_A    0                // 64KB  query tile (128 rows x 512B)
#define OFF_B    65536            // 4 groups x 2 stages x 16KB = 128KB
#define OFF_MRGV 196608           // 128*4*3 f32 = 6144
#define OFF_MRGI 202752           // 128*4*3 int = 6144
#define OFF_SIDX 208896           // 128*3 int = 1536
#define OFF_MBAR 210432           // 4 x 8B mbarriers (one per group)
#define SMEM_TOTAL 210560         // ~206KB -> 1 CTA/SM

// device scratch (no cudaMalloc allowed)
// g_ext layout: [row][64] u64, PRE-SWIZZLED (see prep) -> linear copies only.
__device__ float              g_sq [B_ * N_];
__device__ unsigned long long g_ext[(size_t)B_ * N_ * 64];

typedef unsigned long long u64;

__device__ __forceinline__ uint32_t smem_u32(const void* p) {
    uint32_t a;
    asm("{ .reg .u64 t; cvta.to.shared.u64 t, %1; cvt.u32.u64 %0, t; }"
        : "=r"(a) : "l"(p));
    return a;
}
__device__ __forceinline__ void cpasync16(uint32_t dst, const void* src) {
    asm volatile("cp.async.cg.shared.global [%0], [%1], 16;" :: "r"(dst), "l"(src));
}
#define CP_COMMIT() asm volatile("cp.async.commit_group;" ::: "memory")
#define CP_WAIT0()  asm volatile("cp.async.wait_group 0;" ::: "memory")
#define GROUP_BAR(id) asm volatile("bar.sync %0, 128;" :: "r"(id) : "memory")
#define MBAR_INIT(mb, c) asm volatile("mbarrier.init.shared.b64 [%0], %1;" :: "r"(mb), "r"(c) : "memory")

__device__ __forceinline__ void mbar_wait(uint32_t mb, uint32_t parity) {
    uint32_t done;
    asm volatile("{\n\t.reg .pred p;\n\t"
        "mbarrier.try_wait.parity.acquire.cta.shared::cta.b64 p, [%1], %2;\n\t"
        "selp.b32 %0, 1, 0, p;\n\t}"
        : "=r"(done) : "r"(mb), "r"(parity) : "memory");
    if (!done) {
        asm volatile("{\n\t.reg .pred P1;\n\t"
            "WL_%=:\n\t"
            "mbarrier.try_wait.parity.acquire.cta.shared::cta.b64 P1, [%0], %1, 0x989680;\n\t"
            "@P1 bra.uni WD_%=;\n\t"
            "bra.uni WL_%=;\n\t"
            "WD_%=:\n\t}"
            :: "r"(mb), "r"(parity) : "memory");
    }
}

__device__ __forceinline__ void ldsm4(uint32_t& r0, uint32_t& r1,
                                      uint32_t& r2, uint32_t& r3, uint32_t addr) {
    asm volatile("ldmatrix.sync.aligned.m8n8.x4.shared.b16 {%0,%1,%2,%3}, [%4];"
                 : "=r"(r0), "=r"(r1), "=r"(r2), "=r"(r3) : "r"(addr));
}
__device__ __forceinline__ void mma16816(float& d0, float& d1, float& d2, float& d3,
                                         uint32_t a0, uint32_t a1, uint32_t a2, uint32_t a3,
                                         uint32_t b0, uint32_t b1) {
    asm volatile("mma.sync.aligned.m16n8k16.row.col.f32.f16.f16.f32 "
                 "{%0,%1,%2,%3}, {%4,%5,%6,%7}, {%8,%9}, {%0,%1,%2,%3};"
                 : "+f"(d0), "+f"(d1), "+f"(d2), "+f"(d3)
                 : "r"(a0), "r"(a1), "r"(a2), "r"(a3), "r"(b0), "r"(b1));
}

__device__ __forceinline__ void ins3(float s, int m, float* t, int* ix) {
    if (s < t[2]) {
        if (s < t[1]) {
            t[2] = t[1]; ix[2] = ix[1];
            if (s < t[0]) { t[1] = t[0]; ix[1] = ix[0]; t[0] = s; ix[0] = m; }
            else          { t[1] = s; ix[1] = m; }
        } else { t[2] = s; ix[2] = m; }
    }
}

// ---------------------------------------------------------------------------
// prep: squared norms (fp32) + fp16 hi/lo split -> g_ext (pre-swizzled).
// ---------------------------------------------------------------------------
__global__ void prep_kernel(const float* __restrict__ X) {
    int row  = (blockIdx.x * blockDim.x + threadIdx.x) >> 5;
    int lane = threadIdx.x & 31;
    if (row >= B_ * N_) return;
    float4 v = reinterpret_cast<const float4*>(X)[(size_t)row * 32 + lane];
    float s = v.x * v.x + v.y * v.y + v.z * v.z + v.w * v.w;
    #pragma unroll
    for (int off = 16; off; off >>= 1) s += __shfl_xor_sync(0xffffffffu, s, off);
    if (lane == 0) g_sq[row] = s;

    __half h0 = __float2half_rn(v.x), h1 = __float2half_rn(v.y);
    __half h2 = __float2half_rn(v.z), h3 = __float2half_rn(v.w);
    __half l0 = __float2half_rn(v.x - __half2float(h0));
    __half l1 = __float2half_rn(v.y - __half2float(h1));
    __half l2 = __float2half_rn(v.z - __half2float(h2));
    __half l3 = __float2half_rn(v.w - __half2float(h3));
    u64 hp = (u64)__half_as_ushort(h0)        | ((u64)__half_as_ushort(h1) << 16)
           | ((u64)__half_as_ushort(h2) << 32) | ((u64)__half_as_ushort(h3) << 48);
    u64 lp = (u64)__half_as_ushort(l0)        | ((u64)__half_as_ushort(l1) << 16)
           | ((u64)__half_as_ushort(l2) << 32) | ((u64)__half_as_ushort(l3) << 48);
    int slot = (((lane >> 1) ^ (row & 7)) << 1) + (lane & 1);
    g_ext[(size_t)row * 64 + slot]      = hp;   // hi half (chunks 0..15)
    g_ext[(size_t)row * 64 + 32 + slot] = lp;   // lo half (chunks 16..31)
}

// ---------------------------------------------------------------------------
// main: mma.sync fp16 3-term GEMM (bitwise R10 warp-grid + arithmetic).
// R17: 1 CTA/SM (QT=128, 512 thr), 4 independent 4-warp groups; group g owns
// candidate rows [32g,32g+32) of every tile in a DOUBLE-buffered 2x16KB slice.
// Copy for tile ct+1 issued at top of iteration ct -> hidden under MMA+epi.
// grid (16, 32), warp grid 4(m) x 4(n), warp tile 32x32.
// ---------------------------------------------------------------------------
__global__ __launch_bounds__(NT, 1)
void knn_mma_kernel(const float* __restrict__ X,
                    const float* __restrict__ strength,
                    float* __restrict__ Y) {
    extern __shared__ char smem[];
    const uint32_t sb = smem_u32(smem);
    const int tid  = threadIdx.x;
    const int wid  = tid >> 5;
    const int lane = tid & 31;
    const int b     = blockIdx.y;
    const int qbase = blockIdx.x * QT;
    const int xbase = b * N_;
    const int diagTile = blockIdx.x;      // the only tile containing m==n

    const int grp  = tid >> 7;            // 0..3: group = shared n-range (wid>>2)
    const int lt   = tid & 127;
    const int barid = 1 + grp;
    const uint32_t mbar = sb + OFF_MBAR + grp * 8;
    const uint32_t bSlice = sb + OFF_B + grp * 32768;   // 2 stages x 16KB

    const uint4* E4 = reinterpret_cast<const uint4*>(g_ext);
    float* mrgV = (float*)(smem + OFF_MRGV);
    int*   mrgI = (int*)(smem + OFF_MRGI);
    int*   sIdx = (int*)(smem + OFF_SIDX);

    if (tid < 4) MBAR_INIT(sb + OFF_MBAR + tid * 8, 1);

    // ---- prologue: A (linear, all threads) + B0 slice (per group) ----
    #pragma unroll
    for (int i = 0; i < 8; i++) {
        int li = tid + i * NT;            // 0..4095
        cpasync16(sb + OFF_A + li * 16,
                  &E4[(size_t)(xbase + qbase) * 32 + li]);
    }
    #pragma unroll
    for (int i = 0; i < 8; i++) {
        int c = lt + i * 128;             // 0..1023 within my 16KB slice
        cpasync16(bSlice + c * 16,
                  &E4[(size_t)(xbase + grp * 32) * 32 + c]);
    }
    CP_COMMIT();

    // warp tile position and ldmatrix bases (R10 geometry)
    const int m0 = (wid & 3) * 32;        // 4 m-warps
    const int n0 = (wid >> 2) * 32;       // 4 n-warps (== 32*grp)
    const int rowA = lane & 15;
    const int lcA  = lane >> 4;
    const int rowB = ((lane & 16) >> 1) + (lane & 7);
    const int lcB  = (lane >> 3) & 1;
    const uint32_t rc = (uint32_t)(lane & 7);

    uint32_t aBase[2];
    #pragma unroll
    for (int mi = 0; mi < 2; mi++)
        aBase[mi] = sb + OFF_A + (m0 + mi * 16 + rowA) * 512;
    // group-local B rows: ni2*16 + rowB within the 32-row slice
    uint32_t bBase[2];
    #pragma unroll
    for (int ni2 = 0; ni2 < 2; ni2++)
        bBase[ni2] = bSlice + (ni2 * 16 + rowB) * 512;

    // per-thread rows (4) and their top-3 lists
    const int rr   = lane >> 2;
    const int colb = (lane & 3) * 2;
    int Rl[4] = {m0 + rr, m0 + rr + 8, m0 + 16 + rr, m0 + 24 + rr};
    float tv[4][3];
    int   ti[4][3];
    #pragma unroll
    for (int r = 0; r < 4; r++) {
        tv[r][0] = tv[r][1] = tv[r][2] = 3.0e38f;
        ti[r][0] = ti[r][1] = ti[r][2] = 0;
    }

    CP_WAIT0();
    __syncthreads();   // A + all B0 slices resident; mbarriers initialized

    for (int ct = 0; ct < NTILE; ct++) {
        const uint32_t stageOff = (uint32_t)(ct & 1) * 16384;

        // wait for tile ct (copy index ct-1); tile 0 came from the prologue
        if (ct > 0) mbar_wait(mbar, (uint32_t)((ct - 1) & 1));

        // issue copy for tile ct+1 into the other stage NOW: its last readers
        // were MMA(ct-1), sealed by the group bar at the end of iteration ct-1.
        // The 16KB bulk copy overlaps this whole iteration's MMA + epilogue.
        if (ct < NTILE - 1 && lt == 0) {
            const char* src = (const char*)g_ext
                            + (size_t)(xbase + (ct + 1) * CT + grp * 32) * 512;
            asm volatile("mbarrier.arrive.expect_tx.shared.b64 _, [%0], %1;"
                         :: "r"(mbar), "r"(16384u) : "memory");
            asm volatile("cp.async.bulk.shared::cluster.global.mbarrier::complete_tx::bytes "
                         "[%0], [%1], %2, [%3];"
                         :: "r"(bSlice + ((uint32_t)((ct + 1) & 1) * 16384)),
                            "l"(src), "r"(16384u), "r"(mbar) : "memory");
        }

        // candidate sq for my 8 cols
        float2 q[4];
        #pragma unroll
        for (int ni = 0; ni < 4; ni++)
            q[ni] = __ldg(reinterpret_cast<const float2*>(
                        g_sq + xbase + ct * CT + n0 + ni * 8 + colb));

        // ---- interleaved 3-term MMA, phase-split issue (bitwise R15) ----
        float d[2][4][4];
        #pragma unroll
        for (int mi = 0; mi < 2; mi++)
            #pragma unroll
            for (int ni = 0; ni < 4; ni++)
                #pragma unroll
                for (int e = 0; e < 4; e++) d[mi][ni][e] = 0.f;

        #pragma unroll
        for (int k = 0; k < 8; k++) {
            const uint32_t offA = (((uint32_t)(2 * k + lcA) ^ rc) << 4);
            const uint32_t offB = (((uint32_t)(2 * k + lcB) ^ rc) << 4) + stageOff;
            uint32_t ah[2][4], al[2][4], bh[2][4], bl[2][4];

            #pragma unroll
            for (int mi = 0; mi < 2; mi++)
                ldsm4(ah[mi][0], ah[mi][1], ah[mi][2], ah[mi][3],
                      aBase[mi] + offA);
            #pragma unroll
            for (int ni2 = 0; ni2 < 2; ni2++)
                ldsm4(bh[ni2][0], bh[ni2][1], bh[ni2][2], bh[ni2][3],
                      bBase[ni2] + offB);
            #pragma unroll
            for (int mi = 0; mi < 2; mi++)
                ldsm4(al[mi][0], al[mi][1], al[mi][2], al[mi][3],
                      aBase[mi] + offA + 256);
            #pragma unroll
            for (int ni2 = 0; ni2 < 2; ni2++)
                ldsm4(bl[ni2][0], bl[ni2][1], bl[ni2][2], bl[ni2][3],
                      bBase[ni2] + offB + 256);

            #pragma unroll
            for (int mi = 0; mi < 2; mi++)
                #pragma unroll
                for (int ni = 0; ni < 4; ni++)
                    mma16816(d[mi][ni][0], d[mi][ni][1], d[mi][ni][2], d[mi][ni][3],
                             ah[mi][0], ah[mi][1], ah[mi][2], ah[mi][3],
                             bh[ni >> 1][(ni & 1) * 2], bh[ni >> 1][(ni & 1) * 2 + 1]);
            #pragma unroll
            for (int mi = 0; mi < 2; mi++)
                #pragma unroll
                for (int ni = 0; ni < 4; ni++)
                    mma16816(d[mi][ni][0], d[mi][ni][1], d[mi][ni][2], d[mi][ni][3],
                             ah[mi][0], ah[mi][1], ah[mi][2], ah[mi][3],
                             bl[ni >> 1][(ni & 1) * 2], bl[ni >> 1][(ni & 1) * 2 + 1]);
            #pragma unroll
            for (int mi = 0; mi < 2; mi++)
                #pragma unroll
                for (int ni = 0; ni < 4; ni++)
                    mma16816(d[mi][ni][0], d[mi][ni][1], d[mi][ni][2], d[mi][ni][3],
                             al[mi][0], al[mi][1], al[mi][2], al[mi][3],
                             bh[ni >> 1][(ni & 1) * 2], bh[ni >> 1][(ni & 1) * 2 + 1]);
        }

        // ---- in-register top-3 inserts (32 scores per thread) ----
        if (ct == diagTile) {
            #pragma unroll
            for (int mi = 0; mi < 2; mi++)
                #pragma unroll
                for (int eh = 0; eh < 2; eh++) {
                    const int ri  = mi * 2 + eh;
                    const int ngl = qbase + Rl[ri];
                    #pragma unroll
                    for (int ni = 0; ni < 4; ni++) {
                        int   m  = ct * CT + n0 + ni * 8 + colb;
                        float s0 = fmaf(-2.f, d[mi][ni][eh * 2],     q[ni].x);
                        float s1 = fmaf(-2.f, d[mi][ni][eh * 2 + 1], q[ni].y);
                        if (m != ngl)     ins3(s0, m,     tv[ri], ti[ri]);
                        if (m + 1 != ngl) ins3(s1, m + 1, tv[ri], ti[ri]);
                    }
                }
        } else {
            const int mb0 = ct * CT + n0 + colb;
            #pragma unroll
            for (int mi = 0; mi < 2; mi++)
                #pragma unroll
                for (int eh = 0; eh < 2; eh++) {
                    const int ri = mi * 2 + eh;
                    #pragma unroll
                    for (int ni = 0; ni < 4; ni++) {
                        int   m  = mb0 + ni * 8;
                        float s0 = fmaf(-2.f, d[mi][ni][eh * 2],     q[ni].x);
                        float s1 = fmaf(-2.f, d[mi][ni][eh * 2 + 1], q[ni].y);
                        ins3(s0, m,     tv[ri], ti[ri]);
                        ins3(s1, m + 1, tv[ri], ti[ri]);
                    }
                }
        }

        GROUP_BAR(barid);   // group done with stage ct&1 -> next iter may overwrite
    }

    // ---- merge across the 4 lanes sharing each row: SNAPSHOT then insert ----
    #pragma unroll
    for (int off = 1; off <= 2; off <<= 1) {
        #pragma unroll
        for (int r = 0; r < 4; r++) {
            float sv[3]; int si[3];
            #pragma unroll
            for (int e = 0; e < 3; e++) {
                sv[e] = __shfl_xor_sync(0xffffffffu, tv[r][e], off);
                si[e] = __shfl_xor_sync(0xffffffffu, ti[r][e], off);
            }
            #pragma unroll
            for (int e = 0; e < 3; e++)
                ins3(sv[e], si[e], tv[r], ti[r]);
        }
    }
    // publish per-warp top-3 (4 n-warps per row)
    if ((lane & 3) == 0) {
        const int nw = wid >> 2;
        #pragma unroll
        for (int r = 0; r < 4; r++) {
            int base = (Rl[r] * 4 + nw) * 3;
            #pragma unroll
            for (int e = 0; e < 3; e++) {
                mrgV[base + e] = tv[r][e];
                mrgI[base + e] = ti[r][e];
            }
        }
    }
    __syncthreads();

    // final merge: one thread per row
    if (tid < QT) {
        float ft[3] = {3.0e38f, 3.0e38f, 3.0e38f};
        int   fi[3] = {0, 0, 0};
        #pragma unroll
        for (int nw = 0; nw < 4; nw++) {
            int base = (tid * 4 + nw) * 3;
            #pragma unroll
            for (int e = 0; e < 3; e++)
                ins3(mrgV[base + e], mrgI[base + e], ft, fi);
        }
        sIdx[tid * 3 + 0] = fi[0];
        sIdx[tid * 3 + 1] = fi[1];
        sIdx[tid * 3 + 2] = fi[2];
    }
    __syncthreads();

    // ---- gather + blend: (1-s)*x + (s/3)*(xa+xb+xc), original fp32 data ----
    float s  = fminf(fmaxf(strength[0], 0.f), 1.f);
    float w1 = 1.f - s;
    float w2 = s * (1.f / 3.f);
    const float4* X4 = reinterpret_cast<const float4*>(X + (size_t)b * N_ * D_);
    float* Yb = Y + (size_t)b * N_ * D_;
    for (int r = wid; r < QT; r += NT / 32) {
        int n  = qbase + r;
        int ia = sIdx[r * 3 + 0];
        int ib = sIdx[r * 3 + 1];
        int ic = sIdx[r * 3 + 2];
        float4 vn = X4[(size_t)n  * 32 + lane];
        float4 va = X4[(size_t)ia * 32 + lane];
        float4 vb = X4[(size_t)ib * 32 + lane];
        float4 vc = X4[(size_t)ic * 32 + lane];
        float4 o;
        o.x = w1 * vn.x + w2 * (va.x + vb.x + vc.x);
        o.y = w1 * vn.y + w2 * (va.y + vb.y + vc.y);
        o.z = w1 * vn.z + w2 * (va.z + vb.z + vc.z);
        o.w = w1 * vn.w + w2 * (va.w + vb.w + vc.w);
        reinterpret_cast<float4*>(Yb + (size_t)n * D_)[lane] = o;
    }
}

// ---------------------------------------------------------------------------
extern "C" void kernel_launch(void* const* d_in, const int* in_sizes, int n_in,
                              void* d_out, int out_size) {
    const float* X;
    const float* st;
    if (n_in >= 2 && in_sizes[0] == 1) { st = (const float*)d_in[0]; X = (const float*)d_in[1]; }
    else                               { X = (const float*)d_in[0]; st = (const float*)d_in[1]; }
    float* Y = (float*)d_out;

    int rows = B_ * N_;
    prep_kernel<<<(rows * 32 + 255) / 256, 256>>>(X);

    cudaFuncSetAttribute(knn_mma_kernel,
                         cudaFuncAttributeMaxDynamicSharedMemorySize, SMEM_TOTAL);
    dim3 grid(N_ / QT, B_);
    knn_mma_kernel<<<grid, NT, SMEM_TOTAL>>>(X, st, Y);
}